// round 1
// baseline (speedup 1.0000x reference)
#include <cuda_runtime.h>
#include <math.h>

#define BN   4
#define SEQ  1024
#define CH   768
#define NH   12
#define HD   64
#define ROWS (BN*SEQ)      /* 4096 tokens */
#define QKVC (3*CH)        /* 2304 */
#define BH   (BN*NH)       /* 48  */
#define BETA 0.2f
#define SCALE 0.125f       /* 64^-0.5 */
#define LN_EPS 1e-5f

/* ---- scratch (device globals: allocation-free rule) ---- */
__device__ float g_xn[(size_t)ROWS * CH];
__device__ float g_qkv[(size_t)ROWS * QKVC];
__device__ float g_S[(size_t)BH * SEQ * SEQ];
__device__ float g_P[(size_t)BH * SEQ * SEQ];

/* ================= LayerNorm: one block per token ================= */
__global__ void ln_kernel(const float* __restrict__ x,
                          const float* __restrict__ gamma,
                          const float* __restrict__ beta) {
    int row = blockIdx.x;
    const float* xr = x + (size_t)row * CH;
    float*       orow = g_xn + (size_t)row * CH;
    int t = threadIdx.x;

    float v0 = xr[t], v1 = xr[t + 256], v2 = xr[t + 512];
    float s  = v0 + v1 + v2;
    float sq = v0 * v0 + v1 * v1 + v2 * v2;

    __shared__ float redS[8], redQ[8], stats[2];
    #pragma unroll
    for (int o = 16; o; o >>= 1) {
        s  += __shfl_down_sync(0xffffffffu, s,  o);
        sq += __shfl_down_sync(0xffffffffu, sq, o);
    }
    int w = t >> 5, l = t & 31;
    if (l == 0) { redS[w] = s; redQ[w] = sq; }
    __syncthreads();
    if (t == 0) {
        float S = 0.f, Q = 0.f;
        #pragma unroll
        for (int i = 0; i < 8; i++) { S += redS[i]; Q += redQ[i]; }
        float mu  = S * (1.0f / CH);
        float var = Q * (1.0f / CH) - mu * mu;
        stats[0] = mu;
        stats[1] = rsqrtf(var + LN_EPS);
    }
    __syncthreads();
    float mu = stats[0], rs = stats[1];
    orow[t]       = (v0 - mu) * rs * gamma[t]       + beta[t];
    orow[t + 256] = (v1 - mu) * rs * gamma[t + 256] + beta[t + 256];
    orow[t + 512] = (v2 - mu) * rs * gamma[t + 512] + beta[t + 512];
}

/* ============ QKV GEMM: g_qkv[m,n] = g_xn[m,:] . W[n,:] + b[n] ============ */
/* NT GEMM, 64x64 tile, K-step 16, 256 threads, 4x4 micro-tile */
__global__ void qkv_gemm(const float* __restrict__ W,
                         const float* __restrict__ bias) {
    __shared__ float As[16][65];
    __shared__ float Ws[16][65];
    int m0 = blockIdx.y * 64, n0 = blockIdx.x * 64;
    int t = threadIdx.x, tx = t & 15, ty = t >> 4;
    int r = t >> 2, c4 = (t & 3) * 4;

    float acc[4][4] = {};
    for (int k0 = 0; k0 < CH; k0 += 16) {
        float4 a = *(const float4*)(g_xn + (size_t)(m0 + r) * CH + k0 + c4);
        float4 w = *(const float4*)(W    + (size_t)(n0 + r) * CH + k0 + c4);
        As[c4 + 0][r] = a.x; As[c4 + 1][r] = a.y; As[c4 + 2][r] = a.z; As[c4 + 3][r] = a.w;
        Ws[c4 + 0][r] = w.x; Ws[c4 + 1][r] = w.y; Ws[c4 + 2][r] = w.z; Ws[c4 + 3][r] = w.w;
        __syncthreads();
        #pragma unroll
        for (int kk = 0; kk < 16; kk++) {
            float ra[4], rb[4];
            #pragma unroll
            for (int i = 0; i < 4; i++) ra[i] = As[kk][ty * 4 + i];
            #pragma unroll
            for (int j = 0; j < 4; j++) rb[j] = Ws[kk][tx * 4 + j];
            #pragma unroll
            for (int i = 0; i < 4; i++)
                #pragma unroll
                for (int j = 0; j < 4; j++)
                    acc[i][j] = fmaf(ra[i], rb[j], acc[i][j]);
        }
        __syncthreads();
    }
    #pragma unroll
    for (int i = 0; i < 4; i++) {
        #pragma unroll
        for (int j = 0; j < 4; j++) {
            int n = n0 + tx * 4 + j;
            g_qkv[(size_t)(m0 + ty * 4 + i) * QKVC + n] = acc[i][j] + bias[n];
        }
    }
}

/* ============ Scores: S[bh,i,j] = scale * q_i . k_j ============ */
__global__ void score_gemm() {
    int bh = blockIdx.z, b = bh / NH, h = bh % NH;
    const float* Q = g_qkv + (size_t)b * SEQ * QKVC + h * HD;
    const float* K = g_qkv + (size_t)b * SEQ * QKVC + CH + h * HD;
    float* S = g_S + (size_t)bh * SEQ * SEQ;

    __shared__ float Qs[16][65];
    __shared__ float Ks[16][65];
    int m0 = blockIdx.y * 64, n0 = blockIdx.x * 64;
    int t = threadIdx.x, tx = t & 15, ty = t >> 4;
    int r = t >> 2, c4 = (t & 3) * 4;

    float acc[4][4] = {};
    for (int k0 = 0; k0 < HD; k0 += 16) {
        float4 q = *(const float4*)(Q + (size_t)(m0 + r) * QKVC + k0 + c4);
        float4 k = *(const float4*)(K + (size_t)(n0 + r) * QKVC + k0 + c4);
        Qs[c4 + 0][r] = q.x; Qs[c4 + 1][r] = q.y; Qs[c4 + 2][r] = q.z; Qs[c4 + 3][r] = q.w;
        Ks[c4 + 0][r] = k.x; Ks[c4 + 1][r] = k.y; Ks[c4 + 2][r] = k.z; Ks[c4 + 3][r] = k.w;
        __syncthreads();
        #pragma unroll
        for (int kk = 0; kk < 16; kk++) {
            float ra[4], rb[4];
            #pragma unroll
            for (int i = 0; i < 4; i++) ra[i] = Qs[kk][ty * 4 + i];
            #pragma unroll
            for (int j = 0; j < 4; j++) rb[j] = Ks[kk][tx * 4 + j];
            #pragma unroll
            for (int i = 0; i < 4; i++)
                #pragma unroll
                for (int j = 0; j < 4; j++)
                    acc[i][j] = fmaf(ra[i], rb[j], acc[i][j]);
        }
        __syncthreads();
    }
    #pragma unroll
    for (int i = 0; i < 4; i++)
        #pragma unroll
        for (int j = 0; j < 4; j++)
            S[(size_t)(m0 + ty * 4 + i) * SEQ + n0 + tx * 4 + j] = acc[i][j] * SCALE;
}

/* ============ Lateral inhibition conv + row softmax ============ */
/* attn = (1+B)*S[i][j] - B*(rsum[j-1]+rsum[j]+rsum[j+1]),
   rsum[j] = S[i-1][j]+S[i][j]+S[i+1][j]  (zero padded).          */
__global__ void conv_softmax() {
    int bh = blockIdx.x / SEQ;
    int i  = blockIdx.x % SEQ;
    const float* S = g_S + (size_t)bh * SEQ * SEQ;
    float*       P = g_P + (size_t)bh * SEQ * SEQ + (size_t)i * SEQ;

    __shared__ float rsum[SEQ + 2];
    __shared__ float red[8];
    __shared__ float bcast;

    int t = threadIdx.x;
    const float* mid = S + (size_t)i * SEQ;
    const float* up  = (i > 0)       ? S + (size_t)(i - 1) * SEQ : nullptr;
    const float* dn  = (i < SEQ - 1) ? S + (size_t)(i + 1) * SEQ : nullptr;

    if (t == 0) { rsum[0] = 0.f; rsum[SEQ + 1] = 0.f; }

    float c[4];
    #pragma unroll
    for (int q = 0; q < 4; q++) {
        int j = t + q * 256;
        float m = mid[j];
        c[q] = m;
        float s = m + (up ? up[j] : 0.f) + (dn ? dn[j] : 0.f);
        rsum[j + 1] = s;
    }
    __syncthreads();

    float a[4];
    float mx = -INFINITY;
    #pragma unroll
    for (int q = 0; q < 4; q++) {
        int j = t + q * 256;
        a[q] = (1.0f + BETA) * c[q] - BETA * (rsum[j] + rsum[j + 1] + rsum[j + 2]);
        mx = fmaxf(mx, a[q]);
    }
    /* block max */
    #pragma unroll
    for (int o = 16; o; o >>= 1) mx = fmaxf(mx, __shfl_down_sync(0xffffffffu, mx, o));
    if ((t & 31) == 0) red[t >> 5] = mx;
    __syncthreads();
    if (t == 0) {
        float m = red[0];
        #pragma unroll
        for (int k = 1; k < 8; k++) m = fmaxf(m, red[k]);
        bcast = m;
    }
    __syncthreads();
    float M = bcast;

    float e[4], sum = 0.f;
    #pragma unroll
    for (int q = 0; q < 4; q++) { e[q] = __expf(a[q] - M); sum += e[q]; }
    /* block sum */
    #pragma unroll
    for (int o = 16; o; o >>= 1) sum += __shfl_down_sync(0xffffffffu, sum, o);
    if ((t & 31) == 0) red[t >> 5] = sum;
    __syncthreads();
    if (t == 0) {
        float s = 0.f;
        #pragma unroll
        for (int k = 0; k < 8; k++) s += red[k];
        bcast = 1.0f / s;
    }
    __syncthreads();
    float inv = bcast;
    #pragma unroll
    for (int q = 0; q < 4; q++) P[t + q * 256] = e[q] * inv;
}

/* ============ PV GEMM: out[b, i, h*64+d] = P[bh,i,:] . V[:,d] ============ */
__global__ void pv_gemm(float* __restrict__ out) {
    int bh = blockIdx.y, b = bh / NH, h = bh % NH;
    const float* P = g_P + (size_t)bh * SEQ * SEQ;
    const float* V = g_qkv + (size_t)b * SEQ * QKVC + 2 * CH + h * HD;
    int m0 = blockIdx.x * 64;

    __shared__ float Ps[16][65];
    __shared__ float Vs[16][64];
    int t = threadIdx.x, tx = t & 15, ty = t >> 4;
    int r = t >> 2, c4 = (t & 3) * 4;
    int kr = t >> 4, vc4 = (t & 15) * 4;

    float acc[4][4] = {};
    for (int k0 = 0; k0 < SEQ; k0 += 16) {
        float4 p = *(const float4*)(P + (size_t)(m0 + r) * SEQ + k0 + c4);
        Ps[c4 + 0][r] = p.x; Ps[c4 + 1][r] = p.y; Ps[c4 + 2][r] = p.z; Ps[c4 + 3][r] = p.w;
        float4 v = *(const float4*)(V + (size_t)(k0 + kr) * QKVC + vc4);
        *(float4*)&Vs[kr][vc4] = v;
        __syncthreads();
        #pragma unroll
        for (int kk = 0; kk < 16; kk++) {
            float ra[4], rb[4];
            #pragma unroll
            for (int i = 0; i < 4; i++) ra[i] = Ps[kk][ty * 4 + i];
            #pragma unroll
            for (int j = 0; j < 4; j++) rb[j] = Vs[kk][tx * 4 + j];
            #pragma unroll
            for (int i = 0; i < 4; i++)
                #pragma unroll
                for (int j = 0; j < 4; j++)
                    acc[i][j] = fmaf(ra[i], rb[j], acc[i][j]);
        }
        __syncthreads();
    }
    #pragma unroll
    for (int i = 0; i < 4; i++)
        #pragma unroll
        for (int j = 0; j < 4; j++)
            out[((size_t)b * SEQ + m0 + ty * 4 + i) * CH + h * HD + tx * 4 + j] = acc[i][j];
}

extern "C" void kernel_launch(void* const* d_in, const int* in_sizes, int n_in,
                              void* d_out, int out_size) {
    const float* x     = (const float*)d_in[0];
    const float* qkv_w = (const float*)d_in[1];
    const float* qkv_b = (const float*)d_in[2];
    const float* ln_g  = (const float*)d_in[3];
    const float* ln_b  = (const float*)d_in[4];
    float* out = (float*)d_out;

    ln_kernel<<<ROWS, 256>>>(x, ln_g, ln_b);
    qkv_gemm<<<dim3(QKVC / 64, ROWS / 64), 256>>>(qkv_w, qkv_b);
    score_gemm<<<dim3(SEQ / 64, SEQ / 64, BH), 256>>>();
    conv_softmax<<<BH * SEQ, 256>>>();
    pv_gemm<<<dim3(SEQ / 64, BH), 256>>>(out);
}

// round 2
// speedup vs baseline: 2.2140x; 2.2140x over previous
#include <cuda_runtime.h>
#include <math.h>

#define BN   4
#define SEQ  1024
#define CH   768
#define NH   12
#define HD   64
#define ROWS (BN*SEQ)
#define QKVC (3*CH)
#define BH   (BN*NH)
#define BETA 0.2f
#define SCALE 0.125f
#define LN_EPS 1e-5f

__device__ float g_xn[(size_t)ROWS * CH];
__device__ float g_qkv[(size_t)ROWS * QKVC];
__device__ float g_S[(size_t)BH * SEQ * SEQ];
__device__ float g_P[(size_t)BH * SEQ * SEQ];

__device__ __forceinline__ float to_tf32(float x) {
    unsigned u;
    asm("cvt.rna.tf32.f32 %0, %1;" : "=r"(u) : "f"(x));
    return __uint_as_float(u);
}
__device__ __forceinline__ void mma8(float* c, const float* a, const float* b) {
    asm volatile(
        "mma.sync.aligned.m16n8k8.row.col.f32.tf32.tf32.f32 "
        "{%0,%1,%2,%3}, {%4,%5,%6,%7}, {%8,%9}, {%0,%1,%2,%3};"
        : "+f"(c[0]), "+f"(c[1]), "+f"(c[2]), "+f"(c[3])
        : "r"(__float_as_uint(a[0])), "r"(__float_as_uint(a[1])),
          "r"(__float_as_uint(a[2])), "r"(__float_as_uint(a[3])),
          "r"(__float_as_uint(b[0])), "r"(__float_as_uint(b[1])));
}

/* ================= LayerNorm: one block per token ================= */
__global__ void ln_kernel(const float* __restrict__ x,
                          const float* __restrict__ gamma,
                          const float* __restrict__ beta) {
    int row = blockIdx.x;
    const float* xr = x + (size_t)row * CH;
    float*       orow = g_xn + (size_t)row * CH;
    int t = threadIdx.x;

    float v0 = xr[t], v1 = xr[t + 256], v2 = xr[t + 512];
    float s  = v0 + v1 + v2;
    float sq = v0 * v0 + v1 * v1 + v2 * v2;

    __shared__ float redS[8], redQ[8], stats[2];
    #pragma unroll
    for (int o = 16; o; o >>= 1) {
        s  += __shfl_down_sync(0xffffffffu, s,  o);
        sq += __shfl_down_sync(0xffffffffu, sq, o);
    }
    int w = t >> 5, l = t & 31;
    if (l == 0) { redS[w] = s; redQ[w] = sq; }
    __syncthreads();
    if (t == 0) {
        float S = 0.f, Q = 0.f;
        #pragma unroll
        for (int i = 0; i < 8; i++) { S += redS[i]; Q += redQ[i]; }
        float mu  = S * (1.0f / CH);
        float var = Q * (1.0f / CH) - mu * mu;
        stats[0] = mu;
        stats[1] = rsqrtf(var + LN_EPS);
    }
    __syncthreads();
    float mu = stats[0], rs = stats[1];
    orow[t]       = (v0 - mu) * rs * gamma[t]       + beta[t];
    orow[t + 256] = (v1 - mu) * rs * gamma[t + 256] + beta[t + 256];
    orow[t + 512] = (v2 - mu) * rs * gamma[t + 512] + beta[t + 512];
}

/* ========== QKV GEMM (tf32 MMA) ========== */
__global__ void qkv_gemm(const float* __restrict__ W,
                         const float* __restrict__ bias) {
    __shared__ float As[128][20];
    __shared__ float Bs[64][20];
    int m0 = blockIdx.y * 128, n0 = blockIdx.x * 64;
    int t = threadIdx.x;
    int warp = t >> 5, lane = t & 31, lr = lane >> 2, lc = lane & 3;
    int wm = (warp >> 1) * 32, wn = (warp & 1) * 32;
    int r = t >> 2, c4 = (t & 3) * 4;

    float acc[2][4][4] = {};
    for (int k0 = 0; k0 < CH; k0 += 16) {
        float4 a0 = *(const float4*)(g_xn + (size_t)(m0 + r) * CH + k0 + c4);
        float4 a1 = *(const float4*)(g_xn + (size_t)(m0 + r + 64) * CH + k0 + c4);
        float4 bb = *(const float4*)(W    + (size_t)(n0 + r) * CH + k0 + c4);
        As[r][c4+0]=to_tf32(a0.x); As[r][c4+1]=to_tf32(a0.y); As[r][c4+2]=to_tf32(a0.z); As[r][c4+3]=to_tf32(a0.w);
        As[r+64][c4+0]=to_tf32(a1.x); As[r+64][c4+1]=to_tf32(a1.y); As[r+64][c4+2]=to_tf32(a1.z); As[r+64][c4+3]=to_tf32(a1.w);
        Bs[r][c4+0]=to_tf32(bb.x); Bs[r][c4+1]=to_tf32(bb.y); Bs[r][c4+2]=to_tf32(bb.z); Bs[r][c4+3]=to_tf32(bb.w);
        __syncthreads();
        #pragma unroll
        for (int kc = 0; kc < 2; kc++) {
            int kb = kc * 8;
            float a[2][4], b[4][2];
            #pragma unroll
            for (int mi = 0; mi < 2; mi++) {
                a[mi][0] = As[wm + mi*16 + lr    ][kb + lc];
                a[mi][1] = As[wm + mi*16 + lr + 8][kb + lc];
                a[mi][2] = As[wm + mi*16 + lr    ][kb + lc + 4];
                a[mi][3] = As[wm + mi*16 + lr + 8][kb + lc + 4];
            }
            #pragma unroll
            for (int ni = 0; ni < 4; ni++) {
                b[ni][0] = Bs[wn + ni*8 + lr][kb + lc];
                b[ni][1] = Bs[wn + ni*8 + lr][kb + lc + 4];
            }
            #pragma unroll
            for (int mi = 0; mi < 2; mi++)
                #pragma unroll
                for (int ni = 0; ni < 4; ni++)
                    mma8(acc[mi][ni], a[mi], b[ni]);
        }
        __syncthreads();
    }
    #pragma unroll
    for (int mi = 0; mi < 2; mi++)
        #pragma unroll
        for (int ni = 0; ni < 4; ni++) {
            int row = m0 + wm + mi*16 + lr;
            int col = n0 + wn + ni*8 + lc*2;
            g_qkv[(size_t)row * QKVC + col    ] = acc[mi][ni][0] + bias[col];
            g_qkv[(size_t)row * QKVC + col + 1] = acc[mi][ni][1] + bias[col+1];
            g_qkv[(size_t)(row+8) * QKVC + col    ] = acc[mi][ni][2] + bias[col];
            g_qkv[(size_t)(row+8) * QKVC + col + 1] = acc[mi][ni][3] + bias[col+1];
        }
}

/* ========== Scores (tf32 MMA) ========== */
__global__ void score_gemm() {
    int bh = blockIdx.z, b = bh / NH, h = bh % NH;
    const float* Q = g_qkv + (size_t)b * SEQ * QKVC + h * HD;
    const float* K = g_qkv + (size_t)b * SEQ * QKVC + CH + h * HD;
    float* S = g_S + (size_t)bh * SEQ * SEQ;

    __shared__ float As[128][20];
    __shared__ float Bs[64][20];
    int m0 = blockIdx.y * 128, n0 = blockIdx.x * 64;
    int t = threadIdx.x;
    int warp = t >> 5, lane = t & 31, lr = lane >> 2, lc = lane & 3;
    int wm = (warp >> 1) * 32, wn = (warp & 1) * 32;
    int r = t >> 2, c4 = (t & 3) * 4;

    float acc[2][4][4] = {};
    for (int k0 = 0; k0 < HD; k0 += 16) {
        float4 a0 = *(const float4*)(Q + (size_t)(m0 + r) * QKVC + k0 + c4);
        float4 a1 = *(const float4*)(Q + (size_t)(m0 + r + 64) * QKVC + k0 + c4);
        float4 bb = *(const float4*)(K + (size_t)(n0 + r) * QKVC + k0 + c4);
        As[r][c4+0]=to_tf32(a0.x); As[r][c4+1]=to_tf32(a0.y); As[r][c4+2]=to_tf32(a0.z); As[r][c4+3]=to_tf32(a0.w);
        As[r+64][c4+0]=to_tf32(a1.x); As[r+64][c4+1]=to_tf32(a1.y); As[r+64][c4+2]=to_tf32(a1.z); As[r+64][c4+3]=to_tf32(a1.w);
        Bs[r][c4+0]=to_tf32(bb.x); Bs[r][c4+1]=to_tf32(bb.y); Bs[r][c4+2]=to_tf32(bb.z); Bs[r][c4+3]=to_tf32(bb.w);
        __syncthreads();
        #pragma unroll
        for (int kc = 0; kc < 2; kc++) {
            int kb = kc * 8;
            float a[2][4], b[4][2];
            #pragma unroll
            for (int mi = 0; mi < 2; mi++) {
                a[mi][0] = As[wm + mi*16 + lr    ][kb + lc];
                a[mi][1] = As[wm + mi*16 + lr + 8][kb + lc];
                a[mi][2] = As[wm + mi*16 + lr    ][kb + lc + 4];
                a[mi][3] = As[wm + mi*16 + lr + 8][kb + lc + 4];
            }
            #pragma unroll
            for (int ni = 0; ni < 4; ni++) {
                b[ni][0] = Bs[wn + ni*8 + lr][kb + lc];
                b[ni][1] = Bs[wn + ni*8 + lr][kb + lc + 4];
            }
            #pragma unroll
            for (int mi = 0; mi < 2; mi++)
                #pragma unroll
                for (int ni = 0; ni < 4; ni++)
                    mma8(acc[mi][ni], a[mi], b[ni]);
        }
        __syncthreads();
    }
    #pragma unroll
    for (int mi = 0; mi < 2; mi++)
        #pragma unroll
        for (int ni = 0; ni < 4; ni++) {
            int row = m0 + wm + mi*16 + lr;
            int col = n0 + wn + ni*8 + lc*2;
            S[(size_t)row * SEQ + col    ] = acc[mi][ni][0] * SCALE;
            S[(size_t)row * SEQ + col + 1] = acc[mi][ni][1] * SCALE;
            S[(size_t)(row+8) * SEQ + col    ] = acc[mi][ni][2] * SCALE;
            S[(size_t)(row+8) * SEQ + col + 1] = acc[mi][ni][3] * SCALE;
        }
}

/* ============ Lateral inhibition conv + row softmax ============ */
__global__ void conv_softmax() {
    int bh = blockIdx.x / SEQ;
    int i  = blockIdx.x % SEQ;
    const float* S = g_S + (size_t)bh * SEQ * SEQ;
    float*       P = g_P + (size_t)bh * SEQ * SEQ + (size_t)i * SEQ;

    __shared__ float rsum[SEQ + 2];
    __shared__ float red[8];
    __shared__ float bcast;

    int t = threadIdx.x;
    const float* mid = S + (size_t)i * SEQ;
    const float* up  = (i > 0)       ? S + (size_t)(i - 1) * SEQ : nullptr;
    const float* dn  = (i < SEQ - 1) ? S + (size_t)(i + 1) * SEQ : nullptr;

    if (t == 0) { rsum[0] = 0.f; rsum[SEQ + 1] = 0.f; }

    float c[4];
    #pragma unroll
    for (int q = 0; q < 4; q++) {
        int j = t + q * 256;
        float m = mid[j];
        c[q] = m;
        rsum[j + 1] = m + (up ? up[j] : 0.f) + (dn ? dn[j] : 0.f);
    }
    __syncthreads();

    float a[4];
    float mx = -INFINITY;
    #pragma unroll
    for (int q = 0; q < 4; q++) {
        int j = t + q * 256;
        a[q] = (1.0f + BETA) * c[q] - BETA * (rsum[j] + rsum[j + 1] + rsum[j + 2]);
        mx = fmaxf(mx, a[q]);
    }
    #pragma unroll
    for (int o = 16; o; o >>= 1) mx = fmaxf(mx, __shfl_down_sync(0xffffffffu, mx, o));
    if ((t & 31) == 0) red[t >> 5] = mx;
    __syncthreads();
    if (t == 0) {
        float m = red[0];
        #pragma unroll
        for (int k = 1; k < 8; k++) m = fmaxf(m, red[k]);
        bcast = m;
    }
    __syncthreads();
    float M = bcast;

    float e[4], sum = 0.f;
    #pragma unroll
    for (int q = 0; q < 4; q++) { e[q] = __expf(a[q] - M); sum += e[q]; }
    #pragma unroll
    for (int o = 16; o; o >>= 1) sum += __shfl_down_sync(0xffffffffu, sum, o);
    if ((t & 31) == 0) red[t >> 5] = sum;
    __syncthreads();
    if (t == 0) {
        float s = 0.f;
        #pragma unroll
        for (int k = 0; k < 8; k++) s += red[k];
        bcast = 1.0f / s;
    }
    __syncthreads();
    float inv = bcast;
    #pragma unroll
    for (int q = 0; q < 4; q++) P[t + q * 256] = e[q] * inv;
}

/* ========== PV GEMM (tf32 MMA): out = P @ V ========== */
__global__ void pv_gemm(float* __restrict__ out) {
    int bh = blockIdx.y, b = bh / NH, h = bh % NH;
    const float* P = g_P + (size_t)bh * SEQ * SEQ;
    const float* V = g_qkv + (size_t)b * SEQ * QKVC + 2 * CH + h * HD;
    int m0 = blockIdx.x * 128;

    __shared__ float As[128][20];
    __shared__ float Vs[16][72];
    int t = threadIdx.x;
    int warp = t >> 5, lane = t & 31, lr = lane >> 2, lc = lane & 3;
    int wm = (warp >> 1) * 32, wn = (warp & 1) * 32;
    int r = t >> 2, c4 = (t & 3) * 4;
    int kr = t >> 4, vc4 = (t & 15) * 4;

    float acc[2][4][4] = {};
    for (int k0 = 0; k0 < SEQ; k0 += 16) {
        float4 a0 = *(const float4*)(P + (size_t)(m0 + r) * SEQ + k0 + c4);
        float4 a1 = *(const float4*)(P + (size_t)(m0 + r + 64) * SEQ + k0 + c4);
        float4 v  = *(const float4*)(V + (size_t)(k0 + kr) * QKVC + vc4);
        As[r][c4+0]=to_tf32(a0.x); As[r][c4+1]=to_tf32(a0.y); As[r][c4+2]=to_tf32(a0.z); As[r][c4+3]=to_tf32(a0.w);
        As[r+64][c4+0]=to_tf32(a1.x); As[r+64][c4+1]=to_tf32(a1.y); As[r+64][c4+2]=to_tf32(a1.z); As[r+64][c4+3]=to_tf32(a1.w);
        Vs[kr][vc4+0]=to_tf32(v.x); Vs[kr][vc4+1]=to_tf32(v.y); Vs[kr][vc4+2]=to_tf32(v.z); Vs[kr][vc4+3]=to_tf32(v.w);
        __syncthreads();
        #pragma unroll
        for (int kc = 0; kc < 2; kc++) {
            int kb = kc * 8;
            float a[2][4], bfr[4][2];
            #pragma unroll
            for (int mi = 0; mi < 2; mi++) {
                a[mi][0] = As[wm + mi*16 + lr    ][kb + lc];
                a[mi][1] = As[wm + mi*16 + lr + 8][kb + lc];
                a[mi][2] = As[wm + mi*16 + lr    ][kb + lc + 4];
                a[mi][3] = As[wm + mi*16 + lr + 8][kb + lc + 4];
            }
            #pragma unroll
            for (int ni = 0; ni < 4; ni++) {
                bfr[ni][0] = Vs[kb + lc    ][wn + ni*8 + lr];
                bfr[ni][1] = Vs[kb + lc + 4][wn + ni*8 + lr];
            }
            #pragma unroll
            for (int mi = 0; mi < 2; mi++)
                #pragma unroll
                for (int ni = 0; ni < 4; ni++)
                    mma8(acc[mi][ni], a[mi], bfr[ni]);
        }
        __syncthreads();
    }
    #pragma unroll
    for (int mi = 0; mi < 2; mi++)
        #pragma unroll
        for (int ni = 0; ni < 4; ni++) {
            int row = m0 + wm + mi*16 + lr;
            int col = wn + ni*8 + lc*2;
            out[((size_t)b * SEQ + row) * CH + h*HD + col    ] = acc[mi][ni][0];
            out[((size_t)b * SEQ + row) * CH + h*HD + col + 1] = acc[mi][ni][1];
            out[((size_t)b * SEQ + row + 8) * CH + h*HD + col    ] = acc[mi][ni][2];
            out[((size_t)b * SEQ + row + 8) * CH + h*HD + col + 1] = acc[mi][ni][3];
        }
}

extern "C" void kernel_launch(void* const* d_in, const int* in_sizes, int n_in,
                              void* d_out, int out_size) {
    const float* x     = (const float*)d_in[0];
    const float* qkv_w = (const float*)d_in[1];
    const float* qkv_b = (const float*)d_in[2];
    const float* ln_g  = (const float*)d_in[3];
    const float* ln_b  = (const float*)d_in[4];
    float* out = (float*)d_out;

    ln_kernel<<<ROWS, 256>>>(x, ln_g, ln_b);
    qkv_gemm<<<dim3(QKVC / 64, ROWS / 128), 256>>>(qkv_w, qkv_b);
    score_gemm<<<dim3(SEQ / 64, SEQ / 128, BH), 256>>>();
    conv_softmax<<<BH * SEQ, 256>>>();
    pv_gemm<<<dim3(SEQ / 128, BH), 256>>>(out);
}